// round 1
// baseline (speedup 1.0000x reference)
#include <cuda_runtime.h>
#include <cuda_bf16.h>

// Problem constants (fixed by setup_inputs)
#define KROWS 4096      // number of kernels K
#define CIN   256       // idx_feat channels
#define CDIM  64        // conv_dims (c)
#define NCLS  53        // NUM_CLASSES
#define HW    524288    // h*w = 512*1024
#define HW2   (HW/2)    // pixel pairs

// Device scratch (no allocations allowed)
__device__ float g_S[NCLS * CIN];    // per-class sums of idx_feat
__device__ float g_cnt[NCLS];        // per-class counts
__device__ float g_ssum[NCLS];       // per-class score sums
__device__ float g_fw[NCLS * CDIM];  // fused weights [53,64]

// ---------------------------------------------------------------------------
// K0: zero accumulators (graph replays require re-zeroing every launch)
// ---------------------------------------------------------------------------
__global__ void zero_kernel() {
    int t = blockIdx.x * 256 + threadIdx.x;
    if (t < NCLS * CIN) g_S[t] = 0.0f;
    if (t < NCLS) { g_cnt[t] = 0.0f; g_ssum[t] = 0.0f; }
}

// ---------------------------------------------------------------------------
// K1: segment-sum of idx_feat rows + counts + score sums
//     grid = KROWS blocks, 256 threads (one per input channel)
// ---------------------------------------------------------------------------
__global__ void segsum_kernel(const float* __restrict__ idx_feat,
                              const int* __restrict__ cate,
                              const float* __restrict__ score) {
    int k = blockIdx.x;
    int i = threadIdx.x;
    int u = cate[k];
    atomicAdd(&g_S[u * CIN + i], idx_feat[k * CIN + i]);
    if (i == 0) {
        atomicAdd(&g_cnt[u], 1.0f);
        atomicAdd(&g_ssum[u], score[k]);
    }
}

// ---------------------------------------------------------------------------
// K2: fused_weight[u][j] = (sum_i S[u][i] * W[j][i]) / cnt[u] + bias[j]
//     also writes unique_cate + fused_score tail of the output
//     grid = NCLS blocks, CDIM threads
// ---------------------------------------------------------------------------
__global__ void finalize_kernel(const float* __restrict__ weight,
                                const float* __restrict__ bias,
                                float* __restrict__ out, long long out_size) {
    int u = blockIdx.x;
    int j = threadIdx.x;
    const float* s = &g_S[u * CIN];
    const float* w = &weight[j * CIN];
    float acc = 0.0f;
    #pragma unroll 8
    for (int i = 0; i < CIN; i++) acc += s[i] * w[i];
    float cnt = g_cnt[u];
    g_fw[u * CDIM + j] = acc / cnt + bias[j];
    if (j == 0 && out_size >= (long long)NCLS * HW + 2 * NCLS) {
        out[(long long)NCLS * HW + u] = (float)u;                 // unique_cate
        out[(long long)NCLS * HW + NCLS + u] = g_ssum[u] / cnt;   // fused_score
    }
}

// ---------------------------------------------------------------------------
// K3: main GEMM  out[u][p] = sum_c fw[u][c] * x[c][p]
//     Pixel-pair vectorized with fma.rn.f32x2 (packed 2xfp32 on the FMA pipe,
//     double the rate of 3-reg FFMA on sm_103a).
//     Each thread: 2 pixels, 53 packed accumulators. Weights live in smem as
//     duplicated 64-bit pairs -> broadcast LDS.64 between the rt=2 FFMA2s.
// ---------------------------------------------------------------------------
__global__ void __launch_bounds__(256, 2)
gemm_kernel(const float* __restrict__ x, float* __restrict__ out) {
    __shared__ unsigned long long ws[NCLS * CDIM];
    for (int t = threadIdx.x; t < NCLS * CDIM; t += 256) {
        unsigned int b = __float_as_uint(g_fw[t]);
        ws[t] = ((unsigned long long)b << 32) | (unsigned long long)b;
    }
    __syncthreads();

    int p = blockIdx.x * 256 + threadIdx.x;   // pair index, 0..HW2-1
    const unsigned long long* __restrict__ x2 =
        reinterpret_cast<const unsigned long long*>(x);
    unsigned long long* __restrict__ o2 =
        reinterpret_cast<unsigned long long*>(out);

    unsigned long long acc[NCLS];
    #pragma unroll
    for (int u = 0; u < NCLS; u++) acc[u] = 0ULL;

    unsigned long long xv = x2[p];            // c = 0
    #pragma unroll 1
    for (int cc = 0; cc < CDIM; cc++) {
        // prefetch next channel's pixel pair (predicated off on last iter)
        unsigned long long xn = 0ULL;
        if (cc + 1 < CDIM) xn = x2[(size_t)(cc + 1) * HW2 + p];
        const unsigned long long* wrow = &ws[cc];
        #pragma unroll
        for (int u = 0; u < NCLS; u++) {
            asm("fma.rn.f32x2 %0, %1, %2, %0;"
                : "+l"(acc[u])
                : "l"(wrow[u * CDIM]), "l"(xv));
        }
        xv = xn;
    }

    #pragma unroll
    for (int u = 0; u < NCLS; u++) {
        o2[(size_t)u * HW2 + p] = acc[u];
    }
}

// ---------------------------------------------------------------------------
// Launch. Input order (metadata): x, idx_feat, weight, bias, pred_cate,
// pred_score, n, c, h, w. All launches on default stream (ordered),
// graph-capturable (kernel launches only).
// ---------------------------------------------------------------------------
extern "C" void kernel_launch(void* const* d_in, const int* in_sizes, int n_in,
                              void* d_out, int out_size) {
    const float* x        = (const float*)d_in[0];
    const float* idx_feat = (const float*)d_in[1];
    const float* weight   = (const float*)d_in[2];
    const float* bias     = (const float*)d_in[3];
    const int*   cate     = (const int*)d_in[4];
    const float* score    = (const float*)d_in[5];
    float* out = (float*)d_out;

    zero_kernel<<<(NCLS * CIN + 255) / 256, 256>>>();
    segsum_kernel<<<KROWS, CIN>>>(idx_feat, cate, score);
    finalize_kernel<<<NCLS, CDIM>>>(weight, bias, out, (long long)out_size);
    gemm_kernel<<<HW2 / 256, 256>>>(x, out);
}